// round 10
// baseline (speedup 1.0000x reference)
#include <cuda_runtime.h>

#define NN   50000
#define NE   800000
#define FIN  128
#define EDIM 16
#define HIDD 64
#define HC1  128
#define NG   50
#define NCLS 2

typedef unsigned long long u64t;

// ---------------- f32x2 packed helpers (sm_103a FFMA2 path) ----------------
__device__ __forceinline__ u64t pack2(float lo, float hi) {
    u64t r;
    asm("mov.b64 %0, {%1, %2};" : "=l"(r)
        : "r"(__float_as_uint(lo)), "r"(__float_as_uint(hi)));
    return r;
}
__device__ __forceinline__ void unpack2(u64t v, float& lo, float& hi) {
    unsigned int a, b;
    asm("mov.b64 {%0, %1}, %2;" : "=r"(a), "=r"(b) : "l"(v));
    lo = __uint_as_float(a);
    hi = __uint_as_float(b);
}
__device__ __forceinline__ u64t fma2(u64t a, u64t b, u64t c) {
    u64t d;
    asm("fma.rn.f32x2 %0, %1, %2, %3;" : "=l"(d) : "l"(a), "l"(b), "l"(c));
    return d;
}

// ---------------- scratch (device globals; allocation-free) ----------------
__device__ float g_xp  [NN * HC1];
__device__ float g_xl1 [NN * HC1];
__device__ float g_xr1 [NN * HC1];
__device__ float g_agg1[NN * HC1];
__device__ float g_h   [NN * HC1];

__device__ float g_xp2 [NN * HIDD];
__device__ float g_xl2 [NN * HIDD];
__device__ float g_xr2 [NN * HIDD];
__device__ float g_agg2[NN * HIDD];
__device__ float g_h2  [NN * HIDD];

// CSR by destination.  Zero-initialized at module load; k_scan re-zeroes
// g_cnt (and stats accumulators) after consuming them, so every execution
// (correctness run + each graph replay) sees the same initial state.
__device__ int  g_cnt[NN];
__device__ int  g_off[NN + 1];
__device__ int  g_cur[NN];
__device__ int2 g_es [NE];   // (orig edge id, src node) in CSR order

__device__ float g_stats1[4 * HC1];
__device__ float g_stats2[4 * HIDD];
__device__ float g_gsum[NG * HIDD];
__device__ float g_gmax[NG * HIDD];
__device__ float g_gcnt[NG];

// ---------------- helpers ----------------
__device__ __forceinline__ int lower_bound_dev(const int* arr, int n, int key) {
    int lo = 0, hi = n;
    while (lo < hi) {
        int mid = (lo + hi) >> 1;
        if (arr[mid] < key) lo = mid + 1; else hi = mid;
    }
    return lo;
}

// ---------------- CSR build ----------------
__global__ void k_hist(const int* __restrict__ dst) {
    int stride = gridDim.x * blockDim.x;
    for (int e = blockIdx.x * blockDim.x + threadIdx.x; e < NE; e += stride)
        atomicAdd(&g_cnt[dst[e]], 1);
}

// prefix-scan of counts -> off/cur; then zero cnt + BN stat accumulators
// (so the next execution starts from the same state).
__global__ void k_scan() {
    __shared__ int sh[1024];
    int t = threadIdx.x;
    const int CH = (NN + 1023) >> 10;
    int base = t * CH;
    int s = 0;
    for (int i = 0; i < CH; i++) { int idx = base + i; if (idx < NN) s += g_cnt[idx]; }
    sh[t] = s;
    __syncthreads();
    for (int off = 1; off < 1024; off <<= 1) {
        int v = (t >= off) ? sh[t - off] : 0;
        __syncthreads();
        sh[t] += v;
        __syncthreads();
    }
    int run = (t == 0) ? 0 : sh[t - 1];
    for (int i = 0; i < CH; i++) {
        int idx = base + i;
        if (idx < NN) {
            g_off[idx] = run;
            g_cur[idx] = run;
            run += g_cnt[idx];
            g_cnt[idx] = 0;          // reset for next execution
        }
    }
    if (t == 1023) g_off[NN] = sh[1023];
    if (t < 2 * HC1)  g_stats1[t] = 0.f;   // BN accumulators
    if (t < 2 * HIDD) g_stats2[t] = 0.f;
}

// ---------------- GEMM body (f32x2 packed inner loop) ----------------
template<int K, int M>
__device__ __forceinline__ void gemm3_body(
        int bx, int by,
        const float* __restrict__ A,
        const float* __restrict__ W0, const float* __restrict__ b0, float* __restrict__ C0,
        const float* __restrict__ W1, const float* __restrict__ b1, float* __restrict__ C1,
        const float* __restrict__ W2, const float* __restrict__ b2, float* __restrict__ C2,
        int n) {
    const float* W    = (by == 0) ? W0 : (by == 1) ? W1 : W2;
    const float* bias = (by == 0) ? b0 : (by == 1) ? b1 : b2;
    float* C          = (by == 0) ? C0 : (by == 1) ? C1 : C2;

    constexpr int CT = M / 8;
    constexpr int RT = 256 / CT;
    constexpr int BM = RT * 8;
    constexpr int BK = 32;

    __shared__ float sA[BK][BM + 4];
    __shared__ float sB[BK][M];

    int tx = threadIdx.x % CT, ty = threadIdx.x / CT;
    int row0 = bx * BM;

    u64t accp[8][4];
#pragma unroll
    for (int i = 0; i < 8; i++)
#pragma unroll
        for (int j = 0; j < 4; j++) accp[i][j] = 0ull;

    for (int k0 = 0; k0 < K; k0 += BK) {
        for (int v = threadIdx.x; v < BM * BK / 4; v += 256) {
            int idx = v * 4;
            int r = idx / BK, kk = idx % BK;
            float4 a = make_float4(0.f, 0.f, 0.f, 0.f);
            if (row0 + r < n) a = *(const float4*)&A[(size_t)(row0 + r) * K + k0 + kk];
            sA[kk + 0][r] = a.x;
            sA[kk + 1][r] = a.y;
            sA[kk + 2][r] = a.z;
            sA[kk + 3][r] = a.w;
        }
        for (int v = threadIdx.x; v < BK * M / 4; v += 256) {
            int idx = v * 4;
            int kk = idx / M, c = idx % M;
            *(float4*)&sB[kk][c] = *(const float4*)&W[(size_t)(k0 + kk) * M + c];
        }
        __syncthreads();
#pragma unroll
        for (int kk = 0; kk < BK; kk++) {
            float4 a0 = *(const float4*)&sA[kk][ty * 8];
            float4 a1 = *(const float4*)&sA[kk][ty * 8 + 4];
            float ra[8] = {a0.x, a0.y, a0.z, a0.w, a1.x, a1.y, a1.z, a1.w};
            const ulonglong2* pb = (const ulonglong2*)&sB[kk][tx * 8];
            ulonglong2 b01 = pb[0];
            ulonglong2 b23 = pb[1];
            u64t rb[4] = {b01.x, b01.y, b23.x, b23.y};
#pragma unroll
            for (int i = 0; i < 8; i++) {
                u64t rap = pack2(ra[i], ra[i]);
#pragma unroll
                for (int j = 0; j < 4; j++) accp[i][j] = fma2(rap, rb[j], accp[i][j]);
            }
        }
        __syncthreads();
    }

    float bb[8];
#pragma unroll
    for (int j = 0; j < 8; j++) bb[j] = bias[tx * 8 + j];
#pragma unroll
    for (int i = 0; i < 8; i++) {
        int r = row0 + ty * 8 + i;
        if (r < n) {
            float o[8];
#pragma unroll
            for (int j = 0; j < 4; j++) unpack2(accp[i][j], o[2 * j], o[2 * j + 1]);
            float4 o0 = make_float4(o[0] + bb[0], o[1] + bb[1], o[2] + bb[2], o[3] + bb[3]);
            float4 o1 = make_float4(o[4] + bb[4], o[5] + bb[5], o[6] + bb[6], o[7] + bb[7]);
            *(float4*)&C[(size_t)r * M + tx * 8]     = o0;
            *(float4*)&C[(size_t)r * M + tx * 8 + 4] = o1;
        }
    }
}

// Layer-1: fused CSR-scatter + triple GEMM (independent work, one launch).
#define SCAT_BLOCKS 1024
#define GEMM1_BX ((NN + 127) / 128)   // 391

__global__ void __launch_bounds__(256)
k_scatter_gemm1(const int* __restrict__ src, const int* __restrict__ dst,
                const float* __restrict__ A,
                const float* __restrict__ W0, const float* __restrict__ b0, float* __restrict__ C0,
                const float* __restrict__ W1, const float* __restrict__ b1, float* __restrict__ C1,
                const float* __restrict__ W2, const float* __restrict__ b2, float* __restrict__ C2) {
    if (blockIdx.x < SCAT_BLOCKS) {
        int stride = SCAT_BLOCKS * 256;
        for (int e = blockIdx.x * 256 + threadIdx.x; e < NE; e += stride) {
            int p = atomicAdd(&g_cur[dst[e]], 1);
            g_es[p] = make_int2(e, src[e]);
        }
    } else {
        int gb = blockIdx.x - SCAT_BLOCKS;
        gemm3_body<FIN, HC1>(gb % GEMM1_BX, gb / GEMM1_BX,
                             A, W0, b0, C0, W1, b1, C1, W2, b2, C2, NN);
    }
}

// Layer-2 GEMM (standalone)
__global__ void __launch_bounds__(256)
k_gemm3_l2(const float* __restrict__ A,
           const float* __restrict__ W0, const float* __restrict__ b0, float* __restrict__ C0,
           const float* __restrict__ W1, const float* __restrict__ b1, float* __restrict__ C1,
           const float* __restrict__ W2, const float* __restrict__ b2, float* __restrict__ C2) {
    gemm3_body<HC1, HIDD>(blockIdx.x, blockIdx.y,
                          A, W0, b0, C0, W1, b1, C1, W2, b2, C2, NN);
}

// ---------------- layer-1 GATv2: warp/node, direct exp (clamped), 4-edge batch ------
__device__ __forceinline__ void gat1_edge(
    float& den, float4& acc,
    const float4 ea4, const float4 xl, const float4 xr,
    const u64t (&rWp)[EDIM][2], const float4 rA)
{
    u64t evp0 = 0ull, evp1 = 0ull;
#pragma unroll
    for (int q = 0; q < 4; q++) {
        float e0 = __shfl_sync(0xffffffffu, ea4.x, q);
        float e1 = __shfl_sync(0xffffffffu, ea4.y, q);
        float e2 = __shfl_sync(0xffffffffu, ea4.z, q);
        float e3 = __shfl_sync(0xffffffffu, ea4.w, q);
        u64t p0 = pack2(e0, e0);
        u64t p1 = pack2(e1, e1);
        u64t p2 = pack2(e2, e2);
        u64t p3 = pack2(e3, e3);
        evp0 = fma2(p0, rWp[4 * q + 0][0], evp0); evp1 = fma2(p0, rWp[4 * q + 0][1], evp1);
        evp0 = fma2(p1, rWp[4 * q + 1][0], evp0); evp1 = fma2(p1, rWp[4 * q + 1][1], evp1);
        evp0 = fma2(p2, rWp[4 * q + 2][0], evp0); evp1 = fma2(p2, rWp[4 * q + 2][1], evp1);
        evp0 = fma2(p3, rWp[4 * q + 3][0], evp0); evp1 = fma2(p3, rWp[4 * q + 3][1], evp1);
    }
    float ev0, ev1, ev2, ev3;
    unpack2(evp0, ev0, ev1);
    unpack2(evp1, ev2, ev3);
    float m0 = xl.x + xr.x + ev0, m1 = xl.y + xr.y + ev1;
    float m2 = xl.z + xr.z + ev2, m3 = xl.w + xr.w + ev3;
    m0 = (m0 > 0.f) ? m0 : 0.2f * m0;
    m1 = (m1 > 0.f) ? m1 : 0.2f * m1;
    m2 = (m2 > 0.f) ? m2 : 0.2f * m2;
    m3 = (m3 > 0.f) ? m3 : 0.2f * m3;
    float p = m0 * rA.x + m1 * rA.y + m2 * rA.z + m3 * rA.w;
#pragma unroll
    for (int o = 8; o; o >>= 1) p += __shfl_xor_sync(0xffffffffu, p, o);
    p = fminf(fmaxf(p, -60.f), 60.f);
    float a = __expf(p);
    den += a;
    acc.x = fmaf(a, xl.x, acc.x);
    acc.y = fmaf(a, xl.y, acc.y);
    acc.z = fmaf(a, xl.z, acc.z);
    acc.w = fmaf(a, xl.w, acc.w);
}

__global__ void __launch_bounds__(128)
k_gat1(const float* __restrict__ eattr, const float* __restrict__ We,
       const float* __restrict__ att) {
    int lane = threadIdx.x & 31;
    int w = (blockIdx.x * blockDim.x + threadIdx.x) >> 5;
    int nw = (gridDim.x * blockDim.x) >> 5;
    int c0 = lane * 4;

    u64t rWp[EDIM][2];
#pragma unroll
    for (int d = 0; d < EDIM; d++) {
        float4 wv = *(const float4*)&We[d * HC1 + c0];
        rWp[d][0] = pack2(wv.x, wv.y);
        rWp[d][1] = pack2(wv.z, wv.w);
    }
    const float4 rA = *(const float4*)(att + c0);

    for (int node = w; node < NN; node += nw) {
        int beg = g_off[node], end = g_off[node + 1];
        const float4 xr = *(const float4*)&g_xr1[(size_t)node * HC1 + c0];

        float den = 0.f;
        float4 acc = make_float4(0.f, 0.f, 0.f, 0.f);

        int i = beg;
        for (; i + 4 <= end; i += 4) {
            int2 e0 = g_es[i],     e1 = g_es[i + 1];
            int2 e2 = g_es[i + 2], e3 = g_es[i + 3];
            float4 a0 = make_float4(0.f, 0.f, 0.f, 0.f);
            float4 a1 = a0, a2 = a0, a3 = a0;
            if (lane < 4) {
                a0 = *(const float4*)&eattr[(size_t)e0.x * EDIM + lane * 4];
                a1 = *(const float4*)&eattr[(size_t)e1.x * EDIM + lane * 4];
                a2 = *(const float4*)&eattr[(size_t)e2.x * EDIM + lane * 4];
                a3 = *(const float4*)&eattr[(size_t)e3.x * EDIM + lane * 4];
            }
            const float4 x0 = *(const float4*)&g_xl1[(size_t)e0.y * HC1 + c0];
            const float4 x1 = *(const float4*)&g_xl1[(size_t)e1.y * HC1 + c0];
            const float4 x2 = *(const float4*)&g_xl1[(size_t)e2.y * HC1 + c0];
            const float4 x3 = *(const float4*)&g_xl1[(size_t)e3.y * HC1 + c0];
            gat1_edge(den, acc, a0, x0, xr, rWp, rA);
            gat1_edge(den, acc, a1, x1, xr, rWp, rA);
            gat1_edge(den, acc, a2, x2, xr, rWp, rA);
            gat1_edge(den, acc, a3, x3, xr, rWp, rA);
        }
        for (; i < end; i++) {
            int2 e0 = g_es[i];
            float4 a0 = make_float4(0.f, 0.f, 0.f, 0.f);
            if (lane < 4) a0 = *(const float4*)&eattr[(size_t)e0.x * EDIM + lane * 4];
            const float4 x0 = *(const float4*)&g_xl1[(size_t)e0.y * HC1 + c0];
            gat1_edge(den, acc, a0, x0, xr, rWp, rA);
        }

        float inv = 1.f / (den + 1e-16f);
        *(float4*)&g_agg1[(size_t)node * HC1 + c0] =
            make_float4(acc.x * inv, acc.y * inv, acc.z * inv, acc.w * inv);
    }
}

// ---------------- layer-2 GATv2: warp/node, direct exp (clamped), 4-edge batch ------
__device__ __forceinline__ void gat2_edge(
    float& den, float2& acc,
    const float4 ea4, const float2 xl, const float2 xr,
    const u64t (&rWp)[EDIM], const float2 rA)
{
    u64t evp = 0ull;
#pragma unroll
    for (int q = 0; q < 4; q++) {
        float e0 = __shfl_sync(0xffffffffu, ea4.x, q);
        float e1 = __shfl_sync(0xffffffffu, ea4.y, q);
        float e2 = __shfl_sync(0xffffffffu, ea4.z, q);
        float e3 = __shfl_sync(0xffffffffu, ea4.w, q);
        evp = fma2(pack2(e0, e0), rWp[4 * q + 0], evp);
        evp = fma2(pack2(e1, e1), rWp[4 * q + 1], evp);
        evp = fma2(pack2(e2, e2), rWp[4 * q + 2], evp);
        evp = fma2(pack2(e3, e3), rWp[4 * q + 3], evp);
    }
    float ev0, ev1;
    unpack2(evp, ev0, ev1);
    float m0 = xl.x + xr.x + ev0, m1 = xl.y + xr.y + ev1;
    m0 = (m0 > 0.f) ? m0 : 0.2f * m0;
    m1 = (m1 > 0.f) ? m1 : 0.2f * m1;
    float p = m0 * rA.x + m1 * rA.y;
#pragma unroll
    for (int o = 16; o; o >>= 1) p += __shfl_xor_sync(0xffffffffu, p, o);
    p = fminf(fmaxf(p, -60.f), 60.f);
    float a = __expf(p);
    den += a;
    acc.x = fmaf(a, xl.x, acc.x);
    acc.y = fmaf(a, xl.y, acc.y);
}

__global__ void __launch_bounds__(128)
k_gat2(const float* __restrict__ eattr, const float* __restrict__ We,
       const float* __restrict__ att) {
    int lane = threadIdx.x & 31;
    int w = (blockIdx.x * blockDim.x + threadIdx.x) >> 5;
    int nw = (gridDim.x * blockDim.x) >> 5;
    int c0 = lane * 2;

    u64t rWp[EDIM];
#pragma unroll
    for (int d = 0; d < EDIM; d++)
        rWp[d] = pack2(We[d * HIDD + c0], We[d * HIDD + c0 + 1]);
    const float2 rA = *(const float2*)(att + c0);

    for (int node = w; node < NN; node += nw) {
        int beg = g_off[node], end = g_off[node + 1];
        const float2 xr = *(const float2*)&g_xr2[(size_t)node * HIDD + c0];

        float den = 0.f;
        float2 acc = make_float2(0.f, 0.f);

        int i = beg;
        for (; i + 4 <= end; i += 4) {
            int2 e0 = g_es[i],     e1 = g_es[i + 1];
            int2 e2 = g_es[i + 2], e3 = g_es[i + 3];
            float4 a0 = make_float4(0.f, 0.f, 0.f, 0.f);
            float4 a1 = a0, a2 = a0, a3 = a0;
            if (lane < 4) {
                a0 = *(const float4*)&eattr[(size_t)e0.x * EDIM + lane * 4];
                a1 = *(const float4*)&eattr[(size_t)e1.x * EDIM + lane * 4];
                a2 = *(const float4*)&eattr[(size_t)e2.x * EDIM + lane * 4];
                a3 = *(const float4*)&eattr[(size_t)e3.x * EDIM + lane * 4];
            }
            const float2 x0 = *(const float2*)&g_xl2[(size_t)e0.y * HIDD + c0];
            const float2 x1 = *(const float2*)&g_xl2[(size_t)e1.y * HIDD + c0];
            const float2 x2 = *(const float2*)&g_xl2[(size_t)e2.y * HIDD + c0];
            const float2 x3 = *(const float2*)&g_xl2[(size_t)e3.y * HIDD + c0];
            gat2_edge(den, acc, a0, x0, xr, rWp, rA);
            gat2_edge(den, acc, a1, x1, xr, rWp, rA);
            gat2_edge(den, acc, a2, x2, xr, rWp, rA);
            gat2_edge(den, acc, a3, x3, xr, rWp, rA);
        }
        for (; i < end; i++) {
            int2 e0 = g_es[i];
            float4 a0 = make_float4(0.f, 0.f, 0.f, 0.f);
            if (lane < 4) a0 = *(const float4*)&eattr[(size_t)e0.x * EDIM + lane * 4];
            const float2 x0 = *(const float2*)&g_xl2[(size_t)e0.y * HIDD + c0];
            gat2_edge(den, acc, a0, x0, xr, rWp, rA);
        }

        float inv = 1.f / (den + 1e-16f);
        *(float2*)&g_agg2[(size_t)node * HIDD + c0] =
            make_float2(acc.x * inv, acc.y * inv);
    }
}

// ---------------- batch norm (training mode, biased var) + ELU + skip ----------------
template<int M>
__global__ void k_bn_stats(const float* __restrict__ X, float* __restrict__ stats) {
    int c = threadIdx.x;
    float s = 0.f, q = 0.f;
    for (int r = blockIdx.x; r < NN; r += gridDim.x) {
        float v = X[(size_t)r * M + c];
        s += v; q += v * v;
    }
    atomicAdd(&stats[c], s);
    atomicAdd(&stats[M + c], q);
}

template<int M>
__global__ void k_bn_final(float* __restrict__ stats) {
    int c = threadIdx.x;
    float mu = stats[c] / (float)NN;
    float var = stats[M + c] / (float)NN - mu * mu;
    stats[2 * M + c] = mu;
    stats[3 * M + c] = rsqrtf(var + 1e-5f);
}

template<int M>
__global__ void k_bn_elu(const float* __restrict__ X, const float* __restrict__ stats,
                         const float* __restrict__ gam, const float* __restrict__ bet,
                         const float* __restrict__ skip, float* __restrict__ out) {
    int stride = gridDim.x * blockDim.x;
    int total = NN * M / 4;
    const float4* X4 = (const float4*)X;
    const float4* S4 = (const float4*)skip;
    float4* O4 = (float4*)out;
    for (int i = blockIdx.x * blockDim.x + threadIdx.x; i < total; i += stride) {
        int c = (i * 4) % M;
        float4 xv = X4[i], sv = S4[i];
        float4 o;
        float v;
        v = (xv.x - stats[2 * M + c])     * stats[3 * M + c]     * gam[c]     + bet[c]     + sv.x;
        o.x = (v > 0.f) ? v : expm1f(v);
        v = (xv.y - stats[2 * M + c + 1]) * stats[3 * M + c + 1] * gam[c + 1] + bet[c + 1] + sv.y;
        o.y = (v > 0.f) ? v : expm1f(v);
        v = (xv.z - stats[2 * M + c + 2]) * stats[3 * M + c + 2] * gam[c + 2] + bet[c + 2] + sv.z;
        o.z = (v > 0.f) ? v : expm1f(v);
        v = (xv.w - stats[2 * M + c + 3]) * stats[3 * M + c + 3] * gam[c + 3] + bet[c + 3] + sv.w;
        o.w = (v > 0.f) ? v : expm1f(v);
        O4[i] = o;
    }
}

// ---------------- pooling (batch is sorted) + classifier ----------------
__global__ void k_pool(const int* __restrict__ batch) {
    int g = blockIdx.x;
    int start = lower_bound_dev(batch, NN, g);
    int end   = lower_bound_dev(batch, NN, g + 1);
    int c = threadIdx.x & 63, sub = threadIdx.x >> 6;
    float s = 0.f, mx = -1e30f;
    for (int r = start + sub; r < end; r += 4) {
        float v = g_h2[(size_t)r * HIDD + c];
        s += v; mx = fmaxf(mx, v);
    }
    __shared__ float sh[256], shm[256];
    sh[threadIdx.x] = s; shm[threadIdx.x] = mx;
    __syncthreads();
    if (sub == 0) {
#pragma unroll
        for (int k = 1; k < 4; k++) {
            s += sh[c + k * 64];
            mx = fmaxf(mx, shm[c + k * 64]);
        }
        g_gsum[g * HIDD + c] = s;
        g_gmax[g * HIDD + c] = mx;
        if (c == 0) g_gcnt[g] = (float)(end - start);
    }
}

__global__ void k_classify(const float* __restrict__ W, const float* __restrict__ b,
                           float* __restrict__ out) {
    int i = threadIdx.x;
    if (i >= NG * NCLS) return;
    int g = i / NCLS, k = i % NCLS;
    float cnt = fmaxf(g_gcnt[g], 1.f);
    float acc = b[k];
#pragma unroll 4
    for (int j = 0; j < HIDD; j++) {
        acc = fmaf(g_gsum[g * HIDD + j] / cnt, W[j * NCLS + k], acc);
        acc = fmaf(g_gmax[g * HIDD + j], W[(HIDD + j) * NCLS + k], acc);
    }
    out[i] = acc;
}

// ---------------- launch ----------------
extern "C" void kernel_launch(void* const* d_in, const int* in_sizes, int n_in,
                              void* d_out, int out_size) {
    const float* x       = (const float*)d_in[0];
    const int*   eidx    = (const int*)  d_in[1];
    const float* eattr   = (const float*)d_in[2];
    const int*   batch   = (const int*)  d_in[3];
    const float* skip1_w = (const float*)d_in[4];
    const float* skip1_b = (const float*)d_in[5];
    const float* c1_wl   = (const float*)d_in[6];
    const float* c1_bl   = (const float*)d_in[7];
    const float* c1_wr   = (const float*)d_in[8];
    const float* c1_br   = (const float*)d_in[9];
    const float* c1_we   = (const float*)d_in[10];
    const float* c1_att  = (const float*)d_in[11];
    /* d_in[12] c1_bias: cancels inside training-mode BN */
    const float* bn1_g   = (const float*)d_in[13];
    const float* bn1_b   = (const float*)d_in[14];
    const float* skip2_w = (const float*)d_in[15];
    const float* skip2_b = (const float*)d_in[16];
    const float* c2_wl   = (const float*)d_in[17];
    const float* c2_bl   = (const float*)d_in[18];
    const float* c2_wr   = (const float*)d_in[19];
    const float* c2_br   = (const float*)d_in[20];
    const float* c2_we   = (const float*)d_in[21];
    const float* c2_att  = (const float*)d_in[22];
    /* d_in[23] c2_bias: cancels inside training-mode BN */
    const float* bn2_g   = (const float*)d_in[24];
    const float* bn2_b   = (const float*)d_in[25];
    const float* cls_w   = (const float*)d_in[26];
    const float* cls_b   = (const float*)d_in[27];
    const int* src = eidx;
    const int* dst = eidx + NE;
    float* out = (float*)d_out;

    float *p_xp, *p_xl1, *p_xr1, *p_agg1, *p_h, *p_xp2, *p_xl2, *p_xr2, *p_agg2, *p_h2;
    float *p_st1, *p_st2;
    cudaGetSymbolAddress((void**)&p_xp,   g_xp);
    cudaGetSymbolAddress((void**)&p_xl1,  g_xl1);
    cudaGetSymbolAddress((void**)&p_xr1,  g_xr1);
    cudaGetSymbolAddress((void**)&p_agg1, g_agg1);
    cudaGetSymbolAddress((void**)&p_h,    g_h);
    cudaGetSymbolAddress((void**)&p_xp2,  g_xp2);
    cudaGetSymbolAddress((void**)&p_xl2,  g_xl2);
    cudaGetSymbolAddress((void**)&p_xr2,  g_xr2);
    cudaGetSymbolAddress((void**)&p_agg2, g_agg2);
    cudaGetSymbolAddress((void**)&p_h2,   g_h2);
    cudaGetSymbolAddress((void**)&p_st1,  g_stats1);
    cudaGetSymbolAddress((void**)&p_st2,  g_stats2);

    // 1: histogram
    k_hist<<<1024, 256>>>(dst);
    // 2: scan (+ state reset for next execution)
    k_scan<<<1, 1024>>>();
    // 3: fused CSR scatter + layer-1 triple GEMM
    k_scatter_gemm1<<<SCAT_BLOCKS + GEMM1_BX * 3, 256>>>(src, dst, x,
        skip1_w, skip1_b, p_xp,
        c1_wl,   c1_bl,   p_xl1,
        c1_wr,   c1_br,   p_xr1);
    // 4: layer-1 attention (this is the launch ncu captures)
    k_gat1<<<12500, 128>>>(eattr, c1_we, c1_att);

    // BN1 + skip + ELU
    k_bn_stats<HC1><<<512, HC1>>>(p_agg1, p_st1);
    k_bn_final<HC1><<<1, HC1>>>(p_st1);
    k_bn_elu<HC1><<<1024, 256>>>(p_agg1, p_st1, bn1_g, bn1_b, p_xp, p_h);

    // Layer 2 projections
    k_gemm3_l2<<<dim3((NN + 255) / 256, 3), 256>>>(p_h,
        skip2_w, skip2_b, p_xp2,
        c2_wl,   c2_bl,   p_xl2,
        c2_wr,   c2_br,   p_xr2);

    // Layer 2 attention
    k_gat2<<<12500, 128>>>(eattr, c2_we, c2_att);

    // BN2 + skip + ELU
    k_bn_stats<HIDD><<<512, HIDD>>>(p_agg2, p_st2);
    k_bn_final<HIDD><<<1, HIDD>>>(p_st2);
    k_bn_elu<HIDD><<<1024, 256>>>(p_agg2, p_st2, bn2_g, bn2_b, p_xp2, p_h2);

    // Pool + classify
    k_pool<<<NG, 256>>>(batch);
    k_classify<<<1, 128>>>(cls_w, cls_b, out);
}

// round 11
// speedup vs baseline: 1.0176x; 1.0176x over previous
#include <cuda_runtime.h>

#define NN   50000
#define NE   800000
#define FIN  128
#define EDIM 16
#define HIDD 64
#define HC1  128
#define NG   50
#define NCLS 2

typedef unsigned long long u64t;

// ---------------- f32x2 packed helpers (sm_103a FFMA2 path) ----------------
__device__ __forceinline__ u64t pack2(float lo, float hi) {
    u64t r;
    asm("mov.b64 %0, {%1, %2};" : "=l"(r)
        : "r"(__float_as_uint(lo)), "r"(__float_as_uint(hi)));
    return r;
}
__device__ __forceinline__ void unpack2(u64t v, float& lo, float& hi) {
    unsigned int a, b;
    asm("mov.b64 {%0, %1}, %2;" : "=r"(a), "=r"(b) : "l"(v));
    lo = __uint_as_float(a);
    hi = __uint_as_float(b);
}
__device__ __forceinline__ u64t fma2(u64t a, u64t b, u64t c) {
    u64t d;
    asm("fma.rn.f32x2 %0, %1, %2, %3;" : "=l"(d) : "l"(a), "l"(b), "l"(c));
    return d;
}

// ---------------- scratch (device globals; allocation-free) ----------------
__device__ float g_xp  [NN * HC1];
__device__ float g_xl1 [NN * HC1];
__device__ float g_xr1 [NN * HC1];
__device__ float g_agg1[NN * HC1];
__device__ float g_h   [NN * HC1];

__device__ float g_xp2 [NN * HIDD];
__device__ float g_xl2 [NN * HIDD];
__device__ float g_xr2 [NN * HIDD];
__device__ float g_agg2[NN * HIDD];
__device__ float g_h2  [NN * HIDD];

// CSR by destination.  Zero-initialized at module load; k_scan re-zeroes
// g_cnt (and stats accumulators) after consuming them, so every execution
// (correctness run + each graph replay) sees the same initial state.
__device__ int  g_cnt[NN];
__device__ int  g_off[NN + 1];
__device__ int  g_cur[NN];
__device__ int2 g_es [NE];   // (orig edge id, src node) in CSR order

__device__ float g_stats1[4 * HC1];
__device__ float g_stats2[4 * HIDD];
__device__ float g_gsum[NG * HIDD];
__device__ float g_gmax[NG * HIDD];
__device__ float g_gcnt[NG];

// ---------------- helpers ----------------
__device__ __forceinline__ int lower_bound_dev(const int* arr, int n, int key) {
    int lo = 0, hi = n;
    while (lo < hi) {
        int mid = (lo + hi) >> 1;
        if (arr[mid] < key) lo = mid + 1; else hi = mid;
    }
    return lo;
}

// ---------------- CSR build ----------------
__global__ void k_hist(const int* __restrict__ dst) {
    int stride = gridDim.x * blockDim.x;
    for (int e = blockIdx.x * blockDim.x + threadIdx.x; e < NE; e += stride)
        atomicAdd(&g_cnt[dst[e]], 1);
}

// prefix-scan of counts -> off/cur; then zero cnt + BN stat accumulators.
__global__ void k_scan() {
    __shared__ int sh[1024];
    int t = threadIdx.x;
    const int CH = (NN + 1023) >> 10;
    int base = t * CH;
    int s = 0;
    for (int i = 0; i < CH; i++) { int idx = base + i; if (idx < NN) s += g_cnt[idx]; }
    sh[t] = s;
    __syncthreads();
    for (int off = 1; off < 1024; off <<= 1) {
        int v = (t >= off) ? sh[t - off] : 0;
        __syncthreads();
        sh[t] += v;
        __syncthreads();
    }
    int run = (t == 0) ? 0 : sh[t - 1];
    for (int i = 0; i < CH; i++) {
        int idx = base + i;
        if (idx < NN) {
            g_off[idx] = run;
            g_cur[idx] = run;
            run += g_cnt[idx];
            g_cnt[idx] = 0;          // reset for next execution
        }
    }
    if (t == 1023) g_off[NN] = sh[1023];
    if (t < 2 * HC1)  g_stats1[t] = 0.f;
    if (t < 2 * HIDD) g_stats2[t] = 0.f;
}

// ---------------- GEMM body (f32x2 packed inner loop) ----------------
template<int K, int M>
__device__ __forceinline__ void gemm3_body(
        int bx, int by,
        const float* __restrict__ A,
        const float* __restrict__ W0, const float* __restrict__ b0, float* __restrict__ C0,
        const float* __restrict__ W1, const float* __restrict__ b1, float* __restrict__ C1,
        const float* __restrict__ W2, const float* __restrict__ b2, float* __restrict__ C2,
        int n) {
    const float* W    = (by == 0) ? W0 : (by == 1) ? W1 : W2;
    const float* bias = (by == 0) ? b0 : (by == 1) ? b1 : b2;
    float* C          = (by == 0) ? C0 : (by == 1) ? C1 : C2;

    constexpr int CT = M / 8;
    constexpr int RT = 256 / CT;
    constexpr int BM = RT * 8;
    constexpr int BK = 32;

    __shared__ float sA[BK][BM + 4];
    __shared__ float sB[BK][M];

    int tx = threadIdx.x % CT, ty = threadIdx.x / CT;
    int row0 = bx * BM;

    u64t accp[8][4];
#pragma unroll
    for (int i = 0; i < 8; i++)
#pragma unroll
        for (int j = 0; j < 4; j++) accp[i][j] = 0ull;

    for (int k0 = 0; k0 < K; k0 += BK) {
        for (int v = threadIdx.x; v < BM * BK / 4; v += 256) {
            int idx = v * 4;
            int r = idx / BK, kk = idx % BK;
            float4 a = make_float4(0.f, 0.f, 0.f, 0.f);
            if (row0 + r < n) a = *(const float4*)&A[(size_t)(row0 + r) * K + k0 + kk];
            sA[kk + 0][r] = a.x;
            sA[kk + 1][r] = a.y;
            sA[kk + 2][r] = a.z;
            sA[kk + 3][r] = a.w;
        }
        for (int v = threadIdx.x; v < BK * M / 4; v += 256) {
            int idx = v * 4;
            int kk = idx / M, c = idx % M;
            *(float4*)&sB[kk][c] = *(const float4*)&W[(size_t)(k0 + kk) * M + c];
        }
        __syncthreads();
#pragma unroll
        for (int kk = 0; kk < BK; kk++) {
            float4 a0 = *(const float4*)&sA[kk][ty * 8];
            float4 a1 = *(const float4*)&sA[kk][ty * 8 + 4];
            float ra[8] = {a0.x, a0.y, a0.z, a0.w, a1.x, a1.y, a1.z, a1.w};
            const ulonglong2* pb = (const ulonglong2*)&sB[kk][tx * 8];
            ulonglong2 b01 = pb[0];
            ulonglong2 b23 = pb[1];
            u64t rb[4] = {b01.x, b01.y, b23.x, b23.y};
#pragma unroll
            for (int i = 0; i < 8; i++) {
                u64t rap = pack2(ra[i], ra[i]);
#pragma unroll
                for (int j = 0; j < 4; j++) accp[i][j] = fma2(rap, rb[j], accp[i][j]);
            }
        }
        __syncthreads();
    }

    float bb[8];
#pragma unroll
    for (int j = 0; j < 8; j++) bb[j] = bias[tx * 8 + j];
#pragma unroll
    for (int i = 0; i < 8; i++) {
        int r = row0 + ty * 8 + i;
        if (r < n) {
            float o[8];
#pragma unroll
            for (int j = 0; j < 4; j++) unpack2(accp[i][j], o[2 * j], o[2 * j + 1]);
            float4 o0 = make_float4(o[0] + bb[0], o[1] + bb[1], o[2] + bb[2], o[3] + bb[3]);
            float4 o1 = make_float4(o[4] + bb[4], o[5] + bb[5], o[6] + bb[6], o[7] + bb[7]);
            *(float4*)&C[(size_t)r * M + tx * 8]     = o0;
            *(float4*)&C[(size_t)r * M + tx * 8 + 4] = o1;
        }
    }
}

// Layer-1: fused CSR-scatter + triple GEMM (independent work, one launch).
#define SCAT_BLOCKS 1024
#define GEMM1_BX ((NN + 127) / 128)   // 391

__global__ void __launch_bounds__(256)
k_scatter_gemm1(const int* __restrict__ src, const int* __restrict__ dst,
                const float* __restrict__ A,
                const float* __restrict__ W0, const float* __restrict__ b0, float* __restrict__ C0,
                const float* __restrict__ W1, const float* __restrict__ b1, float* __restrict__ C1,
                const float* __restrict__ W2, const float* __restrict__ b2, float* __restrict__ C2) {
    if (blockIdx.x < SCAT_BLOCKS) {
        int stride = SCAT_BLOCKS * 256;
        for (int e = blockIdx.x * 256 + threadIdx.x; e < NE; e += stride) {
            int p = atomicAdd(&g_cur[dst[e]], 1);
            g_es[p] = make_int2(e, src[e]);
        }
    } else {
        int gb = blockIdx.x - SCAT_BLOCKS;
        gemm3_body<FIN, HC1>(gb % GEMM1_BX, gb / GEMM1_BX,
                             A, W0, b0, C0, W1, b1, C1, W2, b2, C2, NN);
    }
}

// Layer-2 GEMM (standalone)
__global__ void __launch_bounds__(256)
k_gemm3_l2(const float* __restrict__ A,
           const float* __restrict__ W0, const float* __restrict__ b0, float* __restrict__ C0,
           const float* __restrict__ W1, const float* __restrict__ b1, float* __restrict__ C1,
           const float* __restrict__ W2, const float* __restrict__ b2, float* __restrict__ C2) {
    gemm3_body<HC1, HIDD>(blockIdx.x, blockIdx.y,
                          A, W0, b0, C0, W1, b1, C1, W2, b2, C2, NN);
}

// ---------------- shared GAT edge kernel body (64 channels per warp) ----------------
// Used by gat1 (per (node, head)) and gat2 (per node). Direct exp with clamp
// (logits ~N(0, sigma<6); clamp +-60 only guards pathological inputs).
__device__ __forceinline__ void gat_edge64(
    float& den, float2& acc,
    const float4 ea4, const float2 xl, const float2 xr,
    const u64t (&rWp)[EDIM], const float2 rA)
{
    u64t evp = 0ull;
#pragma unroll
    for (int q = 0; q < 4; q++) {
        float e0 = __shfl_sync(0xffffffffu, ea4.x, q);
        float e1 = __shfl_sync(0xffffffffu, ea4.y, q);
        float e2 = __shfl_sync(0xffffffffu, ea4.z, q);
        float e3 = __shfl_sync(0xffffffffu, ea4.w, q);
        evp = fma2(pack2(e0, e0), rWp[4 * q + 0], evp);
        evp = fma2(pack2(e1, e1), rWp[4 * q + 1], evp);
        evp = fma2(pack2(e2, e2), rWp[4 * q + 2], evp);
        evp = fma2(pack2(e3, e3), rWp[4 * q + 3], evp);
    }
    float ev0, ev1;
    unpack2(evp, ev0, ev1);
    float m0 = xl.x + xr.x + ev0, m1 = xl.y + xr.y + ev1;
    m0 = (m0 > 0.f) ? m0 : 0.2f * m0;
    m1 = (m1 > 0.f) ? m1 : 0.2f * m1;
    float p = m0 * rA.x + m1 * rA.y;
#pragma unroll
    for (int o = 16; o; o >>= 1) p += __shfl_xor_sync(0xffffffffu, p, o);
    p = fminf(fmaxf(p, -60.f), 60.f);
    float a = __expf(p);
    den += a;
    acc.x = fmaf(a, xl.x, acc.x);
    acc.y = fmaf(a, xl.y, acc.y);
}

// Layer-1: one warp per (node, head). 100k warp-tasks; adjacent warps share a
// node so es/eattr hit L1. Weights: 16 u64 regs (half of the float4 variant).
__global__ void __launch_bounds__(128)
k_gat1(const float* __restrict__ eattr, const float* __restrict__ We,
       const float* __restrict__ att) {
    int lane = threadIdx.x & 31;
    int w = (blockIdx.x * blockDim.x + threadIdx.x) >> 5;
    if (w >= 2 * NN) return;
    int node = w >> 1;
    int c0 = (w & 1) * HIDD + lane * 2;   // channel pair within [0,128)

    u64t rWp[EDIM];
#pragma unroll
    for (int d = 0; d < EDIM; d++) {
        float2 wv = *(const float2*)&We[d * HC1 + c0];
        rWp[d] = pack2(wv.x, wv.y);
    }
    const float2 rA = *(const float2*)(att + c0);

    int beg = g_off[node], end = g_off[node + 1];
    const float2 xr = *(const float2*)&g_xr1[(size_t)node * HC1 + c0];

    float den = 0.f;
    float2 acc = make_float2(0.f, 0.f);

    int i = beg;
    for (; i + 2 <= end; i += 2) {
        int2 e0 = g_es[i];
        int2 e1 = g_es[i + 1];
        float4 a0 = make_float4(0.f, 0.f, 0.f, 0.f);
        float4 a1 = a0;
        if (lane < 4) {
            a0 = *(const float4*)&eattr[(size_t)e0.x * EDIM + lane * 4];
            a1 = *(const float4*)&eattr[(size_t)e1.x * EDIM + lane * 4];
        }
        const float2 x0 = *(const float2*)&g_xl1[(size_t)e0.y * HC1 + c0];
        const float2 x1 = *(const float2*)&g_xl1[(size_t)e1.y * HC1 + c0];
        gat_edge64(den, acc, a0, x0, xr, rWp, rA);
        gat_edge64(den, acc, a1, x1, xr, rWp, rA);
    }
    if (i < end) {
        int2 e0 = g_es[i];
        float4 a0 = make_float4(0.f, 0.f, 0.f, 0.f);
        if (lane < 4) a0 = *(const float4*)&eattr[(size_t)e0.x * EDIM + lane * 4];
        const float2 x0 = *(const float2*)&g_xl1[(size_t)e0.y * HC1 + c0];
        gat_edge64(den, acc, a0, x0, xr, rWp, rA);
    }

    float inv = 1.f / (den + 1e-16f);
    *(float2*)&g_agg1[(size_t)node * HC1 + c0] =
        make_float2(acc.x * inv, acc.y * inv);
}

// Layer-2: one warp per node (H=1, C=64), round-8 proven structure.
__global__ void __launch_bounds__(128)
k_gat2(const float* __restrict__ eattr, const float* __restrict__ We,
       const float* __restrict__ att) {
    int lane = threadIdx.x & 31;
    int w = (blockIdx.x * blockDim.x + threadIdx.x) >> 5;
    int nw = (gridDim.x * blockDim.x) >> 5;
    int c0 = lane * 2;

    u64t rWp[EDIM];
#pragma unroll
    for (int d = 0; d < EDIM; d++)
        rWp[d] = pack2(We[d * HIDD + c0], We[d * HIDD + c0 + 1]);
    const float2 rA = *(const float2*)(att + c0);

    for (int node = w; node < NN; node += nw) {
        int beg = g_off[node], end = g_off[node + 1];
        const float2 xr = *(const float2*)&g_xr2[(size_t)node * HIDD + c0];

        float den = 0.f;
        float2 acc = make_float2(0.f, 0.f);

        int i = beg;
        for (; i + 2 <= end; i += 2) {
            int2 e0 = g_es[i];
            int2 e1 = g_es[i + 1];
            float4 a0 = make_float4(0.f, 0.f, 0.f, 0.f);
            float4 a1 = a0;
            if (lane < 4) {
                a0 = *(const float4*)&eattr[(size_t)e0.x * EDIM + lane * 4];
                a1 = *(const float4*)&eattr[(size_t)e1.x * EDIM + lane * 4];
            }
            const float2 x0 = *(const float2*)&g_xl2[(size_t)e0.y * HIDD + c0];
            const float2 x1 = *(const float2*)&g_xl2[(size_t)e1.y * HIDD + c0];
            gat_edge64(den, acc, a0, x0, xr, rWp, rA);
            gat_edge64(den, acc, a1, x1, xr, rWp, rA);
        }
        if (i < end) {
            int2 e0 = g_es[i];
            float4 a0 = make_float4(0.f, 0.f, 0.f, 0.f);
            if (lane < 4) a0 = *(const float4*)&eattr[(size_t)e0.x * EDIM + lane * 4];
            const float2 x0 = *(const float2*)&g_xl2[(size_t)e0.y * HIDD + c0];
            gat_edge64(den, acc, a0, x0, xr, rWp, rA);
        }

        float inv = 1.f / (den + 1e-16f);
        *(float2*)&g_agg2[(size_t)node * HIDD + c0] =
            make_float2(acc.x * inv, acc.y * inv);
    }
}

// ---------------- batch norm (training mode, biased var) + ELU + skip ----------------
template<int M>
__global__ void k_bn_stats(const float* __restrict__ X, float* __restrict__ stats) {
    int c = threadIdx.x;
    float s = 0.f, q = 0.f;
    for (int r = blockIdx.x; r < NN; r += gridDim.x) {
        float v = X[(size_t)r * M + c];
        s += v; q += v * v;
    }
    atomicAdd(&stats[c], s);
    atomicAdd(&stats[M + c], q);
}

template<int M>
__global__ void k_bn_final(float* __restrict__ stats) {
    int c = threadIdx.x;
    float mu = stats[c] / (float)NN;
    float var = stats[M + c] / (float)NN - mu * mu;
    stats[2 * M + c] = mu;
    stats[3 * M + c] = rsqrtf(var + 1e-5f);
}

template<int M>
__global__ void k_bn_elu(const float* __restrict__ X, const float* __restrict__ stats,
                         const float* __restrict__ gam, const float* __restrict__ bet,
                         const float* __restrict__ skip, float* __restrict__ out) {
    int stride = gridDim.x * blockDim.x;
    int total = NN * M / 4;
    const float4* X4 = (const float4*)X;
    const float4* S4 = (const float4*)skip;
    float4* O4 = (float4*)out;
    for (int i = blockIdx.x * blockDim.x + threadIdx.x; i < total; i += stride) {
        int c = (i * 4) % M;
        float4 xv = X4[i], sv = S4[i];
        float4 o;
        float v;
        v = (xv.x - stats[2 * M + c])     * stats[3 * M + c]     * gam[c]     + bet[c]     + sv.x;
        o.x = (v > 0.f) ? v : expm1f(v);
        v = (xv.y - stats[2 * M + c + 1]) * stats[3 * M + c + 1] * gam[c + 1] + bet[c + 1] + sv.y;
        o.y = (v > 0.f) ? v : expm1f(v);
        v = (xv.z - stats[2 * M + c + 2]) * stats[3 * M + c + 2] * gam[c + 2] + bet[c + 2] + sv.z;
        o.z = (v > 0.f) ? v : expm1f(v);
        v = (xv.w - stats[2 * M + c + 3]) * stats[3 * M + c + 3] * gam[c + 3] + bet[c + 3] + sv.w;
        o.w = (v > 0.f) ? v : expm1f(v);
        O4[i] = o;
    }
}

// ---------------- pooling (batch is sorted) + classifier ----------------
__global__ void k_pool(const int* __restrict__ batch) {
    int g = blockIdx.x;
    int start = lower_bound_dev(batch, NN, g);
    int end   = lower_bound_dev(batch, NN, g + 1);
    int c = threadIdx.x & 63, sub = threadIdx.x >> 6;
    float s = 0.f, mx = -1e30f;
    for (int r = start + sub; r < end; r += 4) {
        float v = g_h2[(size_t)r * HIDD + c];
        s += v; mx = fmaxf(mx, v);
    }
    __shared__ float sh[256], shm[256];
    sh[threadIdx.x] = s; shm[threadIdx.x] = mx;
    __syncthreads();
    if (sub == 0) {
#pragma unroll
        for (int k = 1; k < 4; k++) {
            s += sh[c + k * 64];
            mx = fmaxf(mx, shm[c + k * 64]);
        }
        g_gsum[g * HIDD + c] = s;
        g_gmax[g * HIDD + c] = mx;
        if (c == 0) g_gcnt[g] = (float)(end - start);
    }
}

__global__ void k_classify(const float* __restrict__ W, const float* __restrict__ b,
                           float* __restrict__ out) {
    int i = threadIdx.x;
    if (i >= NG * NCLS) return;
    int g = i / NCLS, k = i % NCLS;
    float cnt = fmaxf(g_gcnt[g], 1.f);
    float acc = b[k];
#pragma unroll 4
    for (int j = 0; j < HIDD; j++) {
        acc = fmaf(g_gsum[g * HIDD + j] / cnt, W[j * NCLS + k], acc);
        acc = fmaf(g_gmax[g * HIDD + j], W[(HIDD + j) * NCLS + k], acc);
    }
    out[i] = acc;
}

// ---------------- launch ----------------
extern "C" void kernel_launch(void* const* d_in, const int* in_sizes, int n_in,
                              void* d_out, int out_size) {
    const float* x       = (const float*)d_in[0];
    const int*   eidx    = (const int*)  d_in[1];
    const float* eattr   = (const float*)d_in[2];
    const int*   batch   = (const int*)  d_in[3];
    const float* skip1_w = (const float*)d_in[4];
    const float* skip1_b = (const float*)d_in[5];
    const float* c1_wl   = (const float*)d_in[6];
    const float* c1_bl   = (const float*)d_in[7];
    const float* c1_wr   = (const float*)d_in[8];
    const float* c1_br   = (const float*)d_in[9];
    const float* c1_we   = (const float*)d_in[10];
    const float* c1_att  = (const float*)d_in[11];
    /* d_in[12] c1_bias: cancels inside training-mode BN */
    const float* bn1_g   = (const float*)d_in[13];
    const float* bn1_b   = (const float*)d_in[14];
    const float* skip2_w = (const float*)d_in[15];
    const float* skip2_b = (const float*)d_in[16];
    const float* c2_wl   = (const float*)d_in[17];
    const float* c2_bl   = (const float*)d_in[18];
    const float* c2_wr   = (const float*)d_in[19];
    const float* c2_br   = (const float*)d_in[20];
    const float* c2_we   = (const float*)d_in[21];
    const float* c2_att  = (const float*)d_in[22];
    /* d_in[23] c2_bias: cancels inside training-mode BN */
    const float* bn2_g   = (const float*)d_in[24];
    const float* bn2_b   = (const float*)d_in[25];
    const float* cls_w   = (const float*)d_in[26];
    const float* cls_b   = (const float*)d_in[27];
    const int* src = eidx;
    const int* dst = eidx + NE;
    float* out = (float*)d_out;

    float *p_xp, *p_xl1, *p_xr1, *p_agg1, *p_h, *p_xp2, *p_xl2, *p_xr2, *p_agg2, *p_h2;
    float *p_st1, *p_st2;
    cudaGetSymbolAddress((void**)&p_xp,   g_xp);
    cudaGetSymbolAddress((void**)&p_xl1,  g_xl1);
    cudaGetSymbolAddress((void**)&p_xr1,  g_xr1);
    cudaGetSymbolAddress((void**)&p_agg1, g_agg1);
    cudaGetSymbolAddress((void**)&p_h,    g_h);
    cudaGetSymbolAddress((void**)&p_xp2,  g_xp2);
    cudaGetSymbolAddress((void**)&p_xl2,  g_xl2);
    cudaGetSymbolAddress((void**)&p_xr2,  g_xr2);
    cudaGetSymbolAddress((void**)&p_agg2, g_agg2);
    cudaGetSymbolAddress((void**)&p_h2,   g_h2);
    cudaGetSymbolAddress((void**)&p_st1,  g_stats1);
    cudaGetSymbolAddress((void**)&p_st2,  g_stats2);

    // 1: histogram
    k_hist<<<1024, 256>>>(dst);
    // 2: scan (+ state reset for next execution)
    k_scan<<<1, 1024>>>();
    // 3: fused CSR scatter + layer-1 triple GEMM
    k_scatter_gemm1<<<SCAT_BLOCKS + GEMM1_BX * 3, 256>>>(src, dst, x,
        skip1_w, skip1_b, p_xp,
        c1_wl,   c1_bl,   p_xl1,
        c1_wr,   c1_br,   p_xr1);
    // 4: layer-1 attention, one warp per (node, head) -> 100k warps
    k_gat1<<<25000, 128>>>(eattr, c1_we, c1_att);

    // BN1 + skip + ELU
    k_bn_stats<HC1><<<512, HC1>>>(p_agg1, p_st1);
    k_bn_final<HC1><<<1, HC1>>>(p_st1);
    k_bn_elu<HC1><<<1024, 256>>>(p_agg1, p_st1, bn1_g, bn1_b, p_xp, p_h);

    // Layer 2 projections
    k_gemm3_l2<<<dim3((NN + 255) / 256, 3), 256>>>(p_h,
        skip2_w, skip2_b, p_xp2,
        c2_wl,   c2_bl,   p_xl2,
        c2_wr,   c2_br,   p_xr2);

    // Layer 2 attention
    k_gat2<<<12500, 128>>>(eattr, c2_we, c2_att);

    // BN2 + skip + ELU
    k_bn_stats<HIDD><<<512, HIDD>>>(p_agg2, p_st2);
    k_bn_final<HIDD><<<1, HIDD>>>(p_st2);
    k_bn_elu<HIDD><<<1024, 256>>>(p_agg2, p_st2, bn2_g, bn2_b, p_xp2, p_h2);

    // Pool + classify
    k_pool<<<NG, 256>>>(batch);
    k_classify<<<1, 128>>>(cls_w, cls_b, out);
}

// round 13
// speedup vs baseline: 1.0812x; 1.0625x over previous
#include <cuda_runtime.h>

#define NN   50000
#define NE   800000
#define FIN  128
#define EDIM 16
#define HIDD 64
#define HC1  128
#define NG   50
#define NCLS 2

typedef unsigned long long u64t;

// ---------------- f32x2 packed helpers (sm_103a FFMA2 path) ----------------
__device__ __forceinline__ u64t pack2(float lo, float hi) {
    u64t r;
    asm("mov.b64 %0, {%1, %2};" : "=l"(r)
        : "r"(__float_as_uint(lo)), "r"(__float_as_uint(hi)));
    return r;
}
__device__ __forceinline__ void unpack2(u64t v, float& lo, float& hi) {
    unsigned int a, b;
    asm("mov.b64 {%0, %1}, %2;" : "=r"(a), "=r"(b) : "l"(v));
    lo = __uint_as_float(a);
    hi = __uint_as_float(b);
}
__device__ __forceinline__ u64t fma2(u64t a, u64t b, u64t c) {
    u64t d;
    asm("fma.rn.f32x2 %0, %1, %2, %3;" : "=l"(d) : "l"(a), "l"(b), "l"(c));
    return d;
}

// ---------------- scratch (device globals; allocation-free) ----------------
__device__ float g_xp  [NN * HC1];
__device__ float g_xl1 [NN * HC1];
__device__ float g_xr1 [NN * HC1];
__device__ float g_agg1[NN * HC1];
__device__ float g_h   [NN * HC1];

__device__ float g_xp2 [NN * HIDD];
__device__ float g_xl2 [NN * HIDD];
__device__ float g_xr2 [NN * HIDD];
__device__ float g_agg2[NN * HIDD];
__device__ float g_h2  [NN * HIDD];

// CSR by destination.  Zero-initialized at module load; k_scan re-zeroes
// g_cnt (and stats accumulators) after consuming them, so every execution
// (correctness run + each graph replay) sees the same initial state.
__device__ int  g_cnt[NN];
__device__ int  g_off[NN + 1];
__device__ int  g_cur[NN];
__device__ int2 g_es [NE];   // (orig edge id, src node) in CSR order

__device__ float g_stats1[4 * HC1];
__device__ float g_stats2[4 * HIDD];
__device__ float g_gsum[NG * HIDD];
__device__ float g_gmax[NG * HIDD];
__device__ float g_gcnt[NG];

// ---------------- helpers ----------------
__device__ __forceinline__ int lower_bound_dev(const int* arr, int n, int key) {
    int lo = 0, hi = n;
    while (lo < hi) {
        int mid = (lo + hi) >> 1;
        if (arr[mid] < key) lo = mid + 1; else hi = mid;
    }
    return lo;
}

// ---------------- CSR build ----------------
__global__ void k_hist(const int* __restrict__ dst) {
    int stride = gridDim.x * blockDim.x;
    for (int e = blockIdx.x * blockDim.x + threadIdx.x; e < NE; e += stride)
        atomicAdd(&g_cnt[dst[e]], 1);
}

// prefix-scan of counts -> off/cur; then zero cnt + BN stat accumulators.
__global__ void k_scan() {
    __shared__ int sh[1024];
    int t = threadIdx.x;
    const int CH = (NN + 1023) >> 10;
    int base = t * CH;
    int s = 0;
    for (int i = 0; i < CH; i++) { int idx = base + i; if (idx < NN) s += g_cnt[idx]; }
    sh[t] = s;
    __syncthreads();
    for (int off = 1; off < 1024; off <<= 1) {
        int v = (t >= off) ? sh[t - off] : 0;
        __syncthreads();
        sh[t] += v;
        __syncthreads();
    }
    int run = (t == 0) ? 0 : sh[t - 1];
    for (int i = 0; i < CH; i++) {
        int idx = base + i;
        if (idx < NN) {
            g_off[idx] = run;
            g_cur[idx] = run;
            run += g_cnt[idx];
            g_cnt[idx] = 0;          // reset for next execution
        }
    }
    if (t == 1023) g_off[NN] = sh[1023];
    if (t < 2 * HC1)  g_stats1[t] = 0.f;
    if (t < 2 * HIDD) g_stats2[t] = 0.f;
}

// ---------------- GEMM body (f32x2 packed inner loop) ----------------
template<int K, int M>
__device__ __forceinline__ void gemm3_body(
        int bx, int by,
        const float* __restrict__ A,
        const float* __restrict__ W0, const float* __restrict__ b0, float* __restrict__ C0,
        const float* __restrict__ W1, const float* __restrict__ b1, float* __restrict__ C1,
        const float* __restrict__ W2, const float* __restrict__ b2, float* __restrict__ C2,
        int n) {
    const float* W    = (by == 0) ? W0 : (by == 1) ? W1 : W2;
    const float* bias = (by == 0) ? b0 : (by == 1) ? b1 : b2;
    float* C          = (by == 0) ? C0 : (by == 1) ? C1 : C2;

    constexpr int CT = M / 8;
    constexpr int RT = 256 / CT;
    constexpr int BM = RT * 8;
    constexpr int BK = 32;

    __shared__ float sA[BK][BM + 4];
    __shared__ float sB[BK][M];

    int tx = threadIdx.x % CT, ty = threadIdx.x / CT;
    int row0 = bx * BM;

    u64t accp[8][4];
#pragma unroll
    for (int i = 0; i < 8; i++)
#pragma unroll
        for (int j = 0; j < 4; j++) accp[i][j] = 0ull;

    for (int k0 = 0; k0 < K; k0 += BK) {
        for (int v = threadIdx.x; v < BM * BK / 4; v += 256) {
            int idx = v * 4;
            int r = idx / BK, kk = idx % BK;
            float4 a = make_float4(0.f, 0.f, 0.f, 0.f);
            if (row0 + r < n) a = *(const float4*)&A[(size_t)(row0 + r) * K + k0 + kk];
            sA[kk + 0][r] = a.x;
            sA[kk + 1][r] = a.y;
            sA[kk + 2][r] = a.z;
            sA[kk + 3][r] = a.w;
        }
        for (int v = threadIdx.x; v < BK * M / 4; v += 256) {
            int idx = v * 4;
            int kk = idx / M, c = idx % M;
            *(float4*)&sB[kk][c] = *(const float4*)&W[(size_t)(k0 + kk) * M + c];
        }
        __syncthreads();
#pragma unroll
        for (int kk = 0; kk < BK; kk++) {
            float4 a0 = *(const float4*)&sA[kk][ty * 8];
            float4 a1 = *(const float4*)&sA[kk][ty * 8 + 4];
            float ra[8] = {a0.x, a0.y, a0.z, a0.w, a1.x, a1.y, a1.z, a1.w};
            const ulonglong2* pb = (const ulonglong2*)&sB[kk][tx * 8];
            ulonglong2 b01 = pb[0];
            ulonglong2 b23 = pb[1];
            u64t rb[4] = {b01.x, b01.y, b23.x, b23.y};
#pragma unroll
            for (int i = 0; i < 8; i++) {
                u64t rap = pack2(ra[i], ra[i]);
#pragma unroll
                for (int j = 0; j < 4; j++) accp[i][j] = fma2(rap, rb[j], accp[i][j]);
            }
        }
        __syncthreads();
    }

    float bb[8];
#pragma unroll
    for (int j = 0; j < 8; j++) bb[j] = bias[tx * 8 + j];
#pragma unroll
    for (int i = 0; i < 8; i++) {
        int r = row0 + ty * 8 + i;
        if (r < n) {
            float o[8];
#pragma unroll
            for (int j = 0; j < 4; j++) unpack2(accp[i][j], o[2 * j], o[2 * j + 1]);
            float4 o0 = make_float4(o[0] + bb[0], o[1] + bb[1], o[2] + bb[2], o[3] + bb[3]);
            float4 o1 = make_float4(o[4] + bb[4], o[5] + bb[5], o[6] + bb[6], o[7] + bb[7]);
            *(float4*)&C[(size_t)r * M + tx * 8]     = o0;
            *(float4*)&C[(size_t)r * M + tx * 8 + 4] = o1;
        }
    }
}

// Layer-1: fused CSR-scatter + triple GEMM (independent work, one launch).
#define SCAT_BLOCKS 1024
#define GEMM1_BX ((NN + 127) / 128)   // 391

__global__ void __launch_bounds__(256)
k_scatter_gemm1(const int* __restrict__ src, const int* __restrict__ dst,
                const float* __restrict__ A,
                const float* __restrict__ W0, const float* __restrict__ b0, float* __restrict__ C0,
                const float* __restrict__ W1, const float* __restrict__ b1, float* __restrict__ C1,
                const float* __restrict__ W2, const float* __restrict__ b2, float* __restrict__ C2) {
    if (blockIdx.x < SCAT_BLOCKS) {
        int stride = SCAT_BLOCKS * 256;
        for (int e = blockIdx.x * 256 + threadIdx.x; e < NE; e += stride) {
            int p = atomicAdd(&g_cur[dst[e]], 1);
            g_es[p] = make_int2(e, src[e]);
        }
    } else {
        int gb = blockIdx.x - SCAT_BLOCKS;
        gemm3_body<FIN, HC1>(gb % GEMM1_BX, gb / GEMM1_BX,
                             A, W0, b0, C0, W1, b1, C1, W2, b2, C2, NN);
    }
}

// Layer-2 GEMM (standalone)
__global__ void __launch_bounds__(256)
k_gemm3_l2(const float* __restrict__ A,
           const float* __restrict__ W0, const float* __restrict__ b0, float* __restrict__ C0,
           const float* __restrict__ W1, const float* __restrict__ b1, float* __restrict__ C1,
           const float* __restrict__ W2, const float* __restrict__ b2, float* __restrict__ C2) {
    gemm3_body<HC1, HIDD>(blockIdx.x, blockIdx.y,
                          A, W0, b0, C0, W1, b1, C1, W2, b2, C2, NN);
}

// ---------------- layer-1 GATv2: warp/node, We in SHARED memory ----------------
// Weights shared per block (8 KB) instead of 64 regs/lane; each weight row is
// loaded once per 2-edge batch and applied to both edges (4 indep. FMA2 chains).
__global__ void __launch_bounds__(128)
k_gat1(const float* __restrict__ eattr, const float* __restrict__ We,
       const float* __restrict__ att) {
    __shared__ float sWe[EDIM * HC1];
    for (int i = threadIdx.x; i < EDIM * HC1; i += 128)
        sWe[i] = We[i];
    __syncthreads();

    int lane = threadIdx.x & 31;
    int w = (blockIdx.x * blockDim.x + threadIdx.x) >> 5;
    int nw = (gridDim.x * blockDim.x) >> 5;
    int c0 = lane * 4;
    const float4 rA = *(const float4*)(att + c0);
    const ulonglong2* sWp = (const ulonglong2*)&sWe[c0];   // row d at sWp[d*(HC1/4)... ]
    // &sWe[d*HC1 + c0] as ulonglong2*: stride per d = HC1 floats = 16 bytes*? (HC1*4/16 = 32 u64t = 16 ulonglong2)

    for (int node = w; node < NN; node += nw) {
        int beg = g_off[node], end = g_off[node + 1];
        const float4 xr = *(const float4*)&g_xr1[(size_t)node * HC1 + c0];

        float den = 0.f;
        float4 acc = make_float4(0.f, 0.f, 0.f, 0.f);

        int i = beg;
        for (; i + 2 <= end; i += 2) {
            int2 e0 = g_es[i];
            int2 e1 = g_es[i + 1];
            float4 eaA = make_float4(0.f, 0.f, 0.f, 0.f);
            float4 eaB = eaA;
            if (lane < 4) {
                eaA = *(const float4*)&eattr[(size_t)e0.x * EDIM + lane * 4];
                eaB = *(const float4*)&eattr[(size_t)e1.x * EDIM + lane * 4];
            }
            const float4 xlA = *(const float4*)&g_xl1[(size_t)e0.y * HC1 + c0];
            const float4 xlB = *(const float4*)&g_xl1[(size_t)e1.y * HC1 + c0];

            u64t evA0 = 0ull, evA1 = 0ull, evB0 = 0ull, evB1 = 0ull;
#pragma unroll
            for (int q = 0; q < 4; q++) {
                float a0 = __shfl_sync(0xffffffffu, eaA.x, q);
                float a1 = __shfl_sync(0xffffffffu, eaA.y, q);
                float a2 = __shfl_sync(0xffffffffu, eaA.z, q);
                float a3 = __shfl_sync(0xffffffffu, eaA.w, q);
                float b0 = __shfl_sync(0xffffffffu, eaB.x, q);
                float b1 = __shfl_sync(0xffffffffu, eaB.y, q);
                float b2 = __shfl_sync(0xffffffffu, eaB.z, q);
                float b3 = __shfl_sync(0xffffffffu, eaB.w, q);
#pragma unroll
                for (int j = 0; j < 4; j++) {
                    int d = 4 * q + j;
                    ulonglong2 wv = *(const ulonglong2*)&sWe[d * HC1 + c0];
                    float av = (j == 0) ? a0 : (j == 1) ? a1 : (j == 2) ? a2 : a3;
                    float bv = (j == 0) ? b0 : (j == 1) ? b1 : (j == 2) ? b2 : b3;
                    u64t pa = pack2(av, av);
                    u64t pb = pack2(bv, bv);
                    evA0 = fma2(pa, wv.x, evA0); evA1 = fma2(pa, wv.y, evA1);
                    evB0 = fma2(pb, wv.x, evB0); evB1 = fma2(pb, wv.y, evB1);
                }
            }
            // edge A
            {
                float ev0, ev1, ev2, ev3;
                unpack2(evA0, ev0, ev1);
                unpack2(evA1, ev2, ev3);
                float m0 = xlA.x + xr.x + ev0, m1 = xlA.y + xr.y + ev1;
                float m2 = xlA.z + xr.z + ev2, m3 = xlA.w + xr.w + ev3;
                m0 = (m0 > 0.f) ? m0 : 0.2f * m0;
                m1 = (m1 > 0.f) ? m1 : 0.2f * m1;
                m2 = (m2 > 0.f) ? m2 : 0.2f * m2;
                m3 = (m3 > 0.f) ? m3 : 0.2f * m3;
                float p = m0 * rA.x + m1 * rA.y + m2 * rA.z + m3 * rA.w;
#pragma unroll
                for (int o = 8; o; o >>= 1) p += __shfl_xor_sync(0xffffffffu, p, o);
                p = fminf(fmaxf(p, -60.f), 60.f);
                float a = __expf(p);
                den += a;
                acc.x = fmaf(a, xlA.x, acc.x);
                acc.y = fmaf(a, xlA.y, acc.y);
                acc.z = fmaf(a, xlA.z, acc.z);
                acc.w = fmaf(a, xlA.w, acc.w);
            }
            // edge B
            {
                float ev0, ev1, ev2, ev3;
                unpack2(evB0, ev0, ev1);
                unpack2(evB1, ev2, ev3);
                float m0 = xlB.x + xr.x + ev0, m1 = xlB.y + xr.y + ev1;
                float m2 = xlB.z + xr.z + ev2, m3 = xlB.w + xr.w + ev3;
                m0 = (m0 > 0.f) ? m0 : 0.2f * m0;
                m1 = (m1 > 0.f) ? m1 : 0.2f * m1;
                m2 = (m2 > 0.f) ? m2 : 0.2f * m2;
                m3 = (m3 > 0.f) ? m3 : 0.2f * m3;
                float p = m0 * rA.x + m1 * rA.y + m2 * rA.z + m3 * rA.w;
#pragma unroll
                for (int o = 8; o; o >>= 1) p += __shfl_xor_sync(0xffffffffu, p, o);
                p = fminf(fmaxf(p, -60.f), 60.f);
                float a = __expf(p);
                den += a;
                acc.x = fmaf(a, xlB.x, acc.x);
                acc.y = fmaf(a, xlB.y, acc.y);
                acc.z = fmaf(a, xlB.z, acc.z);
                acc.w = fmaf(a, xlB.w, acc.w);
            }
        }
        if (i < end) {
            int2 e0 = g_es[i];
            float4 eaA = make_float4(0.f, 0.f, 0.f, 0.f);
            if (lane < 4) eaA = *(const float4*)&eattr[(size_t)e0.x * EDIM + lane * 4];
            const float4 xlA = *(const float4*)&g_xl1[(size_t)e0.y * HC1 + c0];
            u64t evA0 = 0ull, evA1 = 0ull;
#pragma unroll
            for (int q = 0; q < 4; q++) {
                float a0 = __shfl_sync(0xffffffffu, eaA.x, q);
                float a1 = __shfl_sync(0xffffffffu, eaA.y, q);
                float a2 = __shfl_sync(0xffffffffu, eaA.z, q);
                float a3 = __shfl_sync(0xffffffffu, eaA.w, q);
#pragma unroll
                for (int j = 0; j < 4; j++) {
                    int d = 4 * q + j;
                    ulonglong2 wv = *(const ulonglong2*)&sWe[d * HC1 + c0];
                    float av = (j == 0) ? a0 : (j == 1) ? a1 : (j == 2) ? a2 : a3;
                    u64t pa = pack2(av, av);
                    evA0 = fma2(pa, wv.x, evA0); evA1 = fma2(pa, wv.y, evA1);
                }
            }
            float ev0, ev1, ev2, ev3;
            unpack2(evA0, ev0, ev1);
            unpack2(evA1, ev2, ev3);
            float m0 = xlA.x + xr.x + ev0, m1 = xlA.y + xr.y + ev1;
            float m2 = xlA.z + xr.z + ev2, m3 = xlA.w + xr.w + ev3;
            m0 = (m0 > 0.f) ? m0 : 0.2f * m0;
            m1 = (m1 > 0.f) ? m1 : 0.2f * m1;
            m2 = (m2 > 0.f) ? m2 : 0.2f * m2;
            m3 = (m3 > 0.f) ? m3 : 0.2f * m3;
            float p = m0 * rA.x + m1 * rA.y + m2 * rA.z + m3 * rA.w;
#pragma unroll
            for (int o = 8; o; o >>= 1) p += __shfl_xor_sync(0xffffffffu, p, o);
            p = fminf(fmaxf(p, -60.f), 60.f);
            float a = __expf(p);
            den += a;
            acc.x = fmaf(a, xlA.x, acc.x);
            acc.y = fmaf(a, xlA.y, acc.y);
            acc.z = fmaf(a, xlA.z, acc.z);
            acc.w = fmaf(a, xlA.w, acc.w);
        }

        float inv = 1.f / (den + 1e-16f);
        *(float4*)&g_agg1[(size_t)node * HC1 + c0] =
            make_float4(acc.x * inv, acc.y * inv, acc.z * inv, acc.w * inv);
    }
}

// ---------------- layer-2 GATv2: warp/node, We in SHARED memory ----------------
__global__ void __launch_bounds__(128)
k_gat2(const float* __restrict__ eattr, const float* __restrict__ We,
       const float* __restrict__ att) {
    __shared__ float sWe[EDIM * HIDD];
    for (int i = threadIdx.x; i < EDIM * HIDD; i += 128)
        sWe[i] = We[i];
    __syncthreads();

    int lane = threadIdx.x & 31;
    int w = (blockIdx.x * blockDim.x + threadIdx.x) >> 5;
    int nw = (gridDim.x * blockDim.x) >> 5;
    int c0 = lane * 2;
    const float2 rA = *(const float2*)(att + c0);

    for (int node = w; node < NN; node += nw) {
        int beg = g_off[node], end = g_off[node + 1];
        const float2 xr = *(const float2*)&g_xr2[(size_t)node * HIDD + c0];

        float den = 0.f;
        float2 acc = make_float2(0.f, 0.f);

        int i = beg;
        for (; i + 2 <= end; i += 2) {
            int2 e0 = g_es[i];
            int2 e1 = g_es[i + 1];
            float4 eaA = make_float4(0.f, 0.f, 0.f, 0.f);
            float4 eaB = eaA;
            if (lane < 4) {
                eaA = *(const float4*)&eattr[(size_t)e0.x * EDIM + lane * 4];
                eaB = *(const float4*)&eattr[(size_t)e1.x * EDIM + lane * 4];
            }
            const float2 xlA = *(const float2*)&g_xl2[(size_t)e0.y * HIDD + c0];
            const float2 xlB = *(const float2*)&g_xl2[(size_t)e1.y * HIDD + c0];

            u64t evA = 0ull, evB = 0ull;
#pragma unroll
            for (int q = 0; q < 4; q++) {
                float a0 = __shfl_sync(0xffffffffu, eaA.x, q);
                float a1 = __shfl_sync(0xffffffffu, eaA.y, q);
                float a2 = __shfl_sync(0xffffffffu, eaA.z, q);
                float a3 = __shfl_sync(0xffffffffu, eaA.w, q);
                float b0 = __shfl_sync(0xffffffffu, eaB.x, q);
                float b1 = __shfl_sync(0xffffffffu, eaB.y, q);
                float b2 = __shfl_sync(0xffffffffu, eaB.z, q);
                float b3 = __shfl_sync(0xffffffffu, eaB.w, q);
#pragma unroll
                for (int j = 0; j < 4; j++) {
                    int d = 4 * q + j;
                    u64t wv = *(const u64t*)&sWe[d * HIDD + c0];
                    float av = (j == 0) ? a0 : (j == 1) ? a1 : (j == 2) ? a2 : a3;
                    float bv = (j == 0) ? b0 : (j == 1) ? b1 : (j == 2) ? b2 : b3;
                    evA = fma2(pack2(av, av), wv, evA);
                    evB = fma2(pack2(bv, bv), wv, evB);
                }
            }
            // edge A
            {
                float ev0, ev1;
                unpack2(evA, ev0, ev1);
                float m0 = xlA.x + xr.x + ev0, m1 = xlA.y + xr.y + ev1;
                m0 = (m0 > 0.f) ? m0 : 0.2f * m0;
                m1 = (m1 > 0.f) ? m1 : 0.2f * m1;
                float p = m0 * rA.x + m1 * rA.y;
#pragma unroll
                for (int o = 16; o; o >>= 1) p += __shfl_xor_sync(0xffffffffu, p, o);
                p = fminf(fmaxf(p, -60.f), 60.f);
                float a = __expf(p);
                den += a;
                acc.x = fmaf(a, xlA.x, acc.x);
                acc.y = fmaf(a, xlA.y, acc.y);
            }
            // edge B
            {
                float ev0, ev1;
                unpack2(evB, ev0, ev1);
                float m0 = xlB.x + xr.x + ev0, m1 = xlB.y + xr.y + ev1;
                m0 = (m0 > 0.f) ? m0 : 0.2f * m0;
                m1 = (m1 > 0.f) ? m1 : 0.2f * m1;
                float p = m0 * rA.x + m1 * rA.y;
#pragma unroll
                for (int o = 16; o; o >>= 1) p += __shfl_xor_sync(0xffffffffu, p, o);
                p = fminf(fmaxf(p, -60.f), 60.f);
                float a = __expf(p);
                den += a;
                acc.x = fmaf(a, xlB.x, acc.x);
                acc.y = fmaf(a, xlB.y, acc.y);
            }
        }
        if (i < end) {
            int2 e0 = g_es[i];
            float4 eaA = make_float4(0.f, 0.f, 0.f, 0.f);
            if (lane < 4) eaA = *(const float4*)&eattr[(size_t)e0.x * EDIM + lane * 4];
            const float2 xlA = *(const float2*)&g_xl2[(size_t)e0.y * HIDD + c0];
            u64t evA = 0ull;
#pragma unroll
            for (int q = 0; q < 4; q++) {
                float a0 = __shfl_sync(0xffffffffu, eaA.x, q);
                float a1 = __shfl_sync(0xffffffffu, eaA.y, q);
                float a2 = __shfl_sync(0xffffffffu, eaA.z, q);
                float a3 = __shfl_sync(0xffffffffu, eaA.w, q);
#pragma unroll
                for (int j = 0; j < 4; j++) {
                    int d = 4 * q + j;
                    u64t wv = *(const u64t*)&sWe[d * HIDD + c0];
                    float av = (j == 0) ? a0 : (j == 1) ? a1 : (j == 2) ? a2 : a3;
                    evA = fma2(pack2(av, av), wv, evA);
                }
            }
            float ev0, ev1;
            unpack2(evA, ev0, ev1);
            float m0 = xlA.x + xr.x + ev0, m1 = xlA.y + xr.y + ev1;
            m0 = (m0 > 0.f) ? m0 : 0.2f * m0;
            m1 = (m1 > 0.f) ? m1 : 0.2f * m1;
            float p = m0 * rA.x + m1 * rA.y;
#pragma unroll
            for (int o = 16; o; o >>= 1) p += __shfl_xor_sync(0xffffffffu, p, o);
            p = fminf(fmaxf(p, -60.f), 60.f);
            float a = __expf(p);
            den += a;
            acc.x = fmaf(a, xlA.x, acc.x);
            acc.y = fmaf(a, xlA.y, acc.y);
        }

        float inv = 1.f / (den + 1e-16f);
        *(float2*)&g_agg2[(size_t)node * HIDD + c0] =
            make_float2(acc.x * inv, acc.y * inv);
    }
}

// ---------------- batch norm (training mode, biased var) + ELU + skip ----------------
template<int M>
__global__ void k_bn_stats(const float* __restrict__ X, float* __restrict__ stats) {
    int c = threadIdx.x;
    float s = 0.f, q = 0.f;
    for (int r = blockIdx.x; r < NN; r += gridDim.x) {
        float v = X[(size_t)r * M + c];
        s += v; q += v * v;
    }
    atomicAdd(&stats[c], s);
    atomicAdd(&stats[M + c], q);
}

template<int M>
__global__ void k_bn_final(float* __restrict__ stats) {
    int c = threadIdx.x;
    float mu = stats[c] / (float)NN;
    float var = stats[M + c] / (float)NN - mu * mu;
    stats[2 * M + c] = mu;
    stats[3 * M + c] = rsqrtf(var + 1e-5f);
}

template<int M>
__global__ void k_bn_elu(const float* __restrict__ X, const float* __restrict__ stats,
                         const float* __restrict__ gam, const float* __restrict__ bet,
                         const float* __restrict__ skip, float* __restrict__ out) {
    int stride = gridDim.x * blockDim.x;
    int total = NN * M / 4;
    const float4* X4 = (const float4*)X;
    const float4* S4 = (const float4*)skip;
    float4* O4 = (float4*)out;
    for (int i = blockIdx.x * blockDim.x + threadIdx.x; i < total; i += stride) {
        int c = (i * 4) % M;
        float4 xv = X4[i], sv = S4[i];
        float4 o;
        float v;
        v = (xv.x - stats[2 * M + c])     * stats[3 * M + c]     * gam[c]     + bet[c]     + sv.x;
        o.x = (v > 0.f) ? v : expm1f(v);
        v = (xv.y - stats[2 * M + c + 1]) * stats[3 * M + c + 1] * gam[c + 1] + bet[c + 1] + sv.y;
        o.y = (v > 0.f) ? v : expm1f(v);
        v = (xv.z - stats[2 * M + c + 2]) * stats[3 * M + c + 2] * gam[c + 2] + bet[c + 2] + sv.z;
        o.z = (v > 0.f) ? v : expm1f(v);
        v = (xv.w - stats[2 * M + c + 3]) * stats[3 * M + c + 3] * gam[c + 3] + bet[c + 3] + sv.w;
        o.w = (v > 0.f) ? v : expm1f(v);
        O4[i] = o;
    }
}

// ---------------- pooling (batch is sorted) + classifier ----------------
__global__ void k_pool(const int* __restrict__ batch) {
    int g = blockIdx.x;
    int start = lower_bound_dev(batch, NN, g);
    int end   = lower_bound_dev(batch, NN, g + 1);
    int c = threadIdx.x & 63, sub = threadIdx.x >> 6;
    float s = 0.f, mx = -1e30f;
    for (int r = start + sub; r < end; r += 4) {
        float v = g_h2[(size_t)r * HIDD + c];
        s += v; mx = fmaxf(mx, v);
    }
    __shared__ float sh[256], shm[256];
    sh[threadIdx.x] = s; shm[threadIdx.x] = mx;
    __syncthreads();
    if (sub == 0) {
#pragma unroll
        for (int k = 1; k < 4; k++) {
            s += sh[c + k * 64];
            mx = fmaxf(mx, shm[c + k * 64]);
        }
        g_gsum[g * HIDD + c] = s;
        g_gmax[g * HIDD + c] = mx;
        if (c == 0) g_gcnt[g] = (float)(end - start);
    }
}

__global__ void k_classify(const float* __restrict__ W, const float* __restrict__ b,
                           float* __restrict__ out) {
    int i = threadIdx.x;
    if (i >= NG * NCLS) return;
    int g = i / NCLS, k = i % NCLS;
    float cnt = fmaxf(g_gcnt[g], 1.f);
    float acc = b[k];
#pragma unroll 4
    for (int j = 0; j < HIDD; j++) {
        acc = fmaf(g_gsum[g * HIDD + j] / cnt, W[j * NCLS + k], acc);
        acc = fmaf(g_gmax[g * HIDD + j], W[(HIDD + j) * NCLS + k], acc);
    }
    out[i] = acc;
}

// ---------------- launch ----------------
extern "C" void kernel_launch(void* const* d_in, const int* in_sizes, int n_in,
                              void* d_out, int out_size) {
    const float* x       = (const float*)d_in[0];
    const int*   eidx    = (const int*)  d_in[1];
    const float* eattr   = (const float*)d_in[2];
    const int*   batch   = (const int*)  d_in[3];
    const float* skip1_w = (const float*)d_in[4];
    const float* skip1_b = (const float*)d_in[5];
    const float* c1_wl   = (const float*)d_in[6];
    const float* c1_bl   = (const float*)d_in[7];
    const float* c1_wr   = (const float*)d_in[8];
    const float* c1_br   = (const float*)d_in[9];
    const float* c1_we   = (const float*)d_in[10];
    const float* c1_att  = (const float*)d_in[11];
    /* d_in[12] c1_bias: cancels inside training-mode BN */
    const float* bn1_g   = (const float*)d_in[13];
    const float* bn1_b   = (const float*)d_in[14];
    const float* skip2_w = (const float*)d_in[15];
    const float* skip2_b = (const float*)d_in[16];
    const float* c2_wl   = (const float*)d_in[17];
    const float* c2_bl   = (const float*)d_in[18];
    const float* c2_wr   = (const float*)d_in[19];
    const float* c2_br   = (const float*)d_in[20];
    const float* c2_we   = (const float*)d_in[21];
    const float* c2_att  = (const float*)d_in[22];
    /* d_in[23] c2_bias: cancels inside training-mode BN */
    const float* bn2_g   = (const float*)d_in[24];
    const float* bn2_b   = (const float*)d_in[25];
    const float* cls_w   = (const float*)d_in[26];
    const float* cls_b   = (const float*)d_in[27];
    const int* src = eidx;
    const int* dst = eidx + NE;
    float* out = (float*)d_out;

    float *p_xp, *p_xl1, *p_xr1, *p_agg1, *p_h, *p_xp2, *p_xl2, *p_xr2, *p_agg2, *p_h2;
    float *p_st1, *p_st2;
    cudaGetSymbolAddress((void**)&p_xp,   g_xp);
    cudaGetSymbolAddress((void**)&p_xl1,  g_xl1);
    cudaGetSymbolAddress((void**)&p_xr1,  g_xr1);
    cudaGetSymbolAddress((void**)&p_agg1, g_agg1);
    cudaGetSymbolAddress((void**)&p_h,    g_h);
    cudaGetSymbolAddress((void**)&p_xp2,  g_xp2);
    cudaGetSymbolAddress((void**)&p_xl2,  g_xl2);
    cudaGetSymbolAddress((void**)&p_xr2,  g_xr2);
    cudaGetSymbolAddress((void**)&p_agg2, g_agg2);
    cudaGetSymbolAddress((void**)&p_h2,   g_h2);
    cudaGetSymbolAddress((void**)&p_st1,  g_stats1);
    cudaGetSymbolAddress((void**)&p_st2,  g_stats2);

    // 1: histogram
    k_hist<<<1024, 256>>>(dst);
    // 2: scan (+ state reset for next execution)
    k_scan<<<1, 1024>>>();
    // 3: fused CSR scatter + layer-1 triple GEMM
    k_scatter_gemm1<<<SCAT_BLOCKS + GEMM1_BX * 3, 256>>>(src, dst, x,
        skip1_w, skip1_b, p_xp,
        c1_wl,   c1_bl,   p_xl1,
        c1_wr,   c1_br,   p_xr1);
    // 4: layer-1 attention (profiled launch)
    k_gat1<<<12500, 128>>>(eattr, c1_we, c1_att);

    // BN1 + skip + ELU
    k_bn_stats<HC1><<<512, HC1>>>(p_agg1, p_st1);
    k_bn_final<HC1><<<1, HC1>>>(p_st1);
    k_bn_elu<HC1><<<1024, 256>>>(p_agg1, p_st1, bn1_g, bn1_b, p_xp, p_h);

    // Layer 2 projections
    k_gemm3_l2<<<dim3((NN + 255) / 256, 3), 256>>>(p_h,
        skip2_w, skip2_b, p_xp2,
        c2_wl,   c2_bl,   p_xl2,
        c2_wr,   c2_br,   p_xr2);

    // Layer 2 attention
    k_gat2<<<12500, 128>>>(eattr, c2_we, c2_att);

    // BN2 + skip + ELU
    k_bn_stats<HIDD><<<512, HIDD>>>(p_agg2, p_st2);
    k_bn_final<HIDD><<<1, HIDD>>>(p_st2);
    k_bn_elu<HIDD><<<1024, 256>>>(p_agg2, p_st2, bn2_g, bn2_b, p_xp2, p_h2);

    // Pool + classify
    k_pool<<<NG, 256>>>(batch);
    k_classify<<<1, 128>>>(cls_w, cls_b, out);
}